// round 12
// baseline (speedup 1.0000x reference)
#include <cuda_runtime.h>
#include <cuda_fp16.h>
#include <cstdint>
#include <math.h>

// Problem constants
#define BB   2
#define SS   2048
#define DIN  2048
#define NH   8
#define NKV  4
#define HD   256
#define QDIM  (NH*HD)    // 2048
#define KVDIM (NKV*HD)   // 1024
#define FUSED 4096       // q(2048) | k(1024) | v(1024)
#define SCALING 0.0625f
#define EPS 1e-6f

// ---------------------------------------------------------------------------
// Scratch (device globals)
// ---------------------------------------------------------------------------
__device__ float  g_qkv [(size_t)BB*SS*FUSED];   // fp32 pre-norm qkv
__device__ __half g_qkvh[(size_t)BB*SS*FUSED];   // fp16 post-norm/rope qkv
__device__ __half g_xh  [(size_t)BB*SS*DIN];
__device__ __half g_wf  [(size_t)FUSED*DIN];     // fused wq|wk|wv fp16
__device__ __half g_woh [(size_t)DIN*QDIM];
__device__ __half g_ch  [(size_t)BB*SS*QDIM];

// ---------------------------------------------------------------------------
// Helpers
// ---------------------------------------------------------------------------
__device__ __forceinline__ uint32_t smem_to_u32(const void* smem_ptr) {
    uint32_t addr;
    asm("{ .reg .u64 tmp; cvta.to.shared.u64 tmp, %1; cvt.u32.u64 %0, tmp; }"
        : "=r"(addr) : "l"(smem_ptr));
    return addr;
}
__device__ __forceinline__ void ldsm_x4(uint32_t* r, uint32_t addr) {
    asm volatile("ldmatrix.sync.aligned.m8n8.x4.shared.b16 {%0,%1,%2,%3}, [%4];"
                 : "=r"(r[0]), "=r"(r[1]), "=r"(r[2]), "=r"(r[3]) : "r"(addr));
}
__device__ __forceinline__ void ldsm_x4t(uint32_t* r, uint32_t addr) {
    asm volatile("ldmatrix.sync.aligned.m8n8.x4.trans.shared.b16 {%0,%1,%2,%3}, [%4];"
                 : "=r"(r[0]), "=r"(r[1]), "=r"(r[2]), "=r"(r[3]) : "r"(addr));
}
__device__ __forceinline__ void mma_f16(float* d, const uint32_t* a, const uint32_t* b) {
    asm volatile(
        "mma.sync.aligned.m16n8k16.row.col.f32.f16.f16.f32 "
        "{%0,%1,%2,%3}, {%4,%5,%6,%7}, {%8,%9}, {%0,%1,%2,%3};"
        : "+f"(d[0]), "+f"(d[1]), "+f"(d[2]), "+f"(d[3])
        : "r"(a[0]), "r"(a[1]), "r"(a[2]), "r"(a[3]), "r"(b[0]), "r"(b[1]));
}
__device__ __forceinline__ void cp_async16(uint32_t dst, const void* src) {
    asm volatile("cp.async.cg.shared.global [%0], [%1], 16;" :: "r"(dst), "l"(src));
}
__device__ __forceinline__ uint32_t pack_h2(float x0, float x1) {
    __half2 h = __floats2half2_rn(x0, x1);
    return *(uint32_t*)&h;
}

// ---------------------------------------------------------------------------
// Merged fp32 -> fp16 convert (one launch). Regions in float4 units.
// ---------------------------------------------------------------------------
#define CVT_N0 ((BB*SS*DIN)/4)
#define CVT_N1 ((QDIM*DIN)/4)
#define CVT_N2 ((KVDIM*DIN)/4)
#define CVT_N3 ((KVDIM*DIN)/4)
#define CVT_N4 ((DIN*QDIM)/4)
#define CVT_TOT (CVT_N0+CVT_N1+CVT_N2+CVT_N3+CVT_N4)

__global__ void cvt_all(const float* __restrict__ x,  const float* __restrict__ wq,
                        const float* __restrict__ wk, const float* __restrict__ wv,
                        const float* __restrict__ wo) {
    int i = blockIdx.x * blockDim.x + threadIdx.x;
    if (i >= CVT_TOT) return;
    const float* src;
    __half* dst;
    int j = i;
    if (j < CVT_N0) { src = x;  dst = g_xh; }
    else if ((j -= CVT_N0) < CVT_N1) { src = wq; dst = g_wf; }
    else if ((j -= CVT_N1) < CVT_N2) { src = wk; dst = g_wf + (size_t)QDIM * DIN; }
    else if ((j -= CVT_N2) < CVT_N3) { src = wv; dst = g_wf + (size_t)(QDIM + KVDIM) * DIN; }
    else { j -= CVT_N3; src = wo; dst = g_woh; }
    float4 v = ((const float4*)src)[j];
    uint2 r;
    r.x = pack_h2(v.x, v.y);
    r.y = pack_h2(v.z, v.w);
    ((uint2*)dst)[j] = r;
}

// ---------------------------------------------------------------------------
// HMMA GEMM v4 (NT, fp16): tile 128x128, BK=32, 512 threads, 16 warps (4x4),
// warp tile 32x32 (acc 32 regs/thread). 2-stage cp.async (R5-proven pipeline).
// 2 CTAs/SM -> 32 warps/SM = 8 warps/SMSP (occupancy experiment).
// ---------------------------------------------------------------------------
#define HBK 32
#define HPITCH 80
#define HMAT_BYTES (128 * HPITCH)      // 10240
#define HSTAGE_BYTES (2 * HMAT_BYTES)  // 20480
#define HSMEM_BYTES (2 * HSTAGE_BYTES) // 40960

__global__ __launch_bounds__(512, 2)
void gemm_f16(const __half* __restrict__ A, const __half* __restrict__ B,
              float* __restrict__ C, int M, int N, int K) {
    extern __shared__ char smemc[];
    const uint32_t smem = smem_to_u32(smemc);
    const int tid = threadIdx.x;
    const int wid = tid >> 5;
    const int lid = tid & 31;
    const int warp_m = wid & 3;      // 0-3
    const int warp_n = wid >> 2;     // 0-3
    const int m0 = blockIdx.y * 128;
    const int n0 = blockIdx.x * 128;
    const int kchunks = K / HBK;     // 64

    // 1024 granules of 16B per stage (A 512 | B 512); 2 per thread.
#define PREFETCH(cc) do {                                                     \
        const int s_ = (cc) & 1;                                              \
        const int k0_ = (cc) * HBK;                                           \
        _Pragma("unroll")                                                     \
        for (int it = 0; it < 2; it++) {                                      \
            int g = tid + 512 * it;                                           \
            int mat = g >> 9;                                                 \
            int idx = g & 511;                                                \
            int r = idx >> 2;                                                 \
            int q = idx & 3;                                                  \
            int rowg = (mat == 0 ? m0 : n0) + r;                              \
            const __half* src = (mat == 0 ? A : B) + (size_t)rowg * K + k0_ + q * 8; \
            uint32_t dst = smem + s_ * HSTAGE_BYTES + mat * HMAT_BYTES        \
                         + r * HPITCH + q * 16;                               \
            cp_async16(dst, src);                                             \
        }                                                                     \
        asm volatile("cp.async.commit_group;");                               \
    } while (0)

    float acc[2][4][4];
#pragma unroll
    for (int i = 0; i < 2; i++)
#pragma unroll
        for (int j = 0; j < 4; j++)
#pragma unroll
            for (int q = 0; q < 4; q++) acc[i][j][q] = 0.f;

    PREFETCH(0);

    for (int c = 0; c < kchunks; c++) {
        if (c + 1 < kchunks) {
            PREFETCH(c + 1);
            asm volatile("cp.async.wait_group 1;" ::: "memory");
        } else {
            asm volatile("cp.async.wait_group 0;" ::: "memory");
        }
        __syncthreads();

        const uint32_t sA = smem + (c & 1) * HSTAGE_BYTES;
        const uint32_t sB = sA + HMAT_BYTES;

#pragma unroll
        for (int k16 = 0; k16 < 2; k16++) {
            const int kb2 = (k16 * 16 + (lid >> 4) * 8) * 2;   // byte col offset
            // B fragments: 2x ldsm_x4 (n16k16 each) -> 4 n8 frags
            uint32_t bfr[4][2];
#pragma unroll
            for (int j = 0; j < 2; j++) {
                int rb = warp_n * 32 + j * 16 + (lid & 15);
                uint32_t t[4];
                ldsm_x4(t, sB + (uint32_t)(rb * HPITCH) + kb2);
                bfr[2 * j][0]     = t[0]; bfr[2 * j][1]     = t[2];
                bfr[2 * j + 1][0] = t[1]; bfr[2 * j + 1][1] = t[3];
            }
            // A fragments: 2x ldsm_x4 (m16k16 each)
            uint32_t a[2][4];
            {
                int ra = warp_m * 32 + (lid & 15);
#pragma unroll
                for (int i = 0; i < 2; i++)
                    ldsm_x4(a[i], sA + (uint32_t)((ra + i * 16) * HPITCH) + kb2);
            }
#pragma unroll
            for (int i = 0; i < 2; i++)
#pragma unroll
                for (int j = 0; j < 4; j++)
                    mma_f16(acc[i][j], a[i], bfr[j]);
        }
        __syncthreads();
    }

    const int rbase = m0 + warp_m * 32 + (lid >> 2);
    const int cbase = n0 + warp_n * 32 + (lid & 3) * 2;
#pragma unroll
    for (int i = 0; i < 2; i++)
#pragma unroll
        for (int j = 0; j < 4; j++) {
            float* p0 = C + (size_t)(rbase + i * 16) * N + cbase + j * 8;
            float* p1 = C + (size_t)(rbase + i * 16 + 8) * N + cbase + j * 8;
            *(float2*)p0 = make_float2(acc[i][j][0], acc[i][j][1]);
            *(float2*)p1 = make_float2(acc[i][j][2], acc[i][j][3]);
        }
#undef PREFETCH
}

// ---------------------------------------------------------------------------
// RMSNorm + RoPE v2 (unchanged).
// ---------------------------------------------------------------------------
__global__ void rms_rope2(const float* __restrict__ cosp,
                          const float* __restrict__ sinp,
                          const float* __restrict__ qg,
                          const float* __restrict__ kg) {
    const int bs = blockIdx.x;
    const int spos = bs & (SS - 1);
    const int wid = threadIdx.x >> 5, lane = threadIdx.x & 31;
    const int head = blockIdx.y * 8 + wid;   // 0..15

    int col0;
    if (head < 8)       col0 = head * HD;
    else if (head < 12) col0 = 2048 + (head - 8) * HD;
    else                col0 = 3072 + (head - 12) * HD;

    const float* src = g_qkv + (size_t)bs * FUSED + col0;
    __half* dst = g_qkvh + (size_t)bs * FUSED + col0;

    float v[8];
#pragma unroll
    for (int i = 0; i < 8; i++) v[i] = src[lane + 32 * i];

    if (head < 12) {
        float ssum = 0.f;
#pragma unroll
        for (int i = 0; i < 8; i++) ssum += v[i] * v[i];
#pragma unroll
        for (int off = 16; off >= 1; off >>= 1)
            ssum += __shfl_xor_sync(0xffffffffu, ssum, off);
        float rstd = rsqrtf(ssum * (1.0f / HD) + EPS);
        const float* gamma = (head < 8) ? qg : kg;
        float scale = (head < 8) ? SCALING : 1.0f;
        float xn[8];
#pragma unroll
        for (int i = 0; i < 8; i++)
            xn[i] = v[i] * rstd * (1.0f + gamma[lane + 32 * i]);
#pragma unroll
        for (int i = 0; i < 8; i++) {
            int d = lane + 32 * i;
            float rot = (i < 4) ? -xn[i + 4] : xn[i - 4];
            float o = (xn[i] * cosp[(size_t)spos * HD + d]
                     + rot * sinp[(size_t)spos * HD + d]) * scale;
            dst[d] = __float2half(o);
        }
    } else {
#pragma unroll
        for (int i = 0; i < 8; i++)
            dst[lane + 32 * i] = __float2half(v[i]);
    }
}

// ---------------------------------------------------------------------------
// Flash attention v3 (unchanged, 142 us measured): complementary-paired
// q-tiles, BM=128, BN=64, 256 threads, 128 CTAs (single wave).
// ---------------------------------------------------------------------------
#define FPITCH 528
#define FQTILE (128 * FPITCH)               // 67584
#define FKTILE (64 * FPITCH)                // 33792
#define FSMEM_BYTES (FQTILE + 2 * FKTILE)   // 135168

__global__ __launch_bounds__(256)
void flash_f16(const __half* __restrict__ qh, const __half* __restrict__ kh,
               const __half* __restrict__ vh, __half* __restrict__ ch) {
    extern __shared__ char smemc[];
    const uint32_t smem = smem_to_u32(smemc);
    const uint32_t sQ = smem;
    const uint32_t sK = smem + FQTILE;
    const uint32_t sV = smem + FQTILE + FKTILE;

    const int pairIdx = blockIdx.x;          // 0..7
    const int h = blockIdx.y, b = blockIdx.z;
    const int kvh = h >> 1;
    const int tid = threadIdx.x, wid = tid >> 5, lid = tid & 31;

    const int ra = wid * 16 + (lid & 15);
    const int rq = (lid >> 2);

#define LOAD_KV(dst, src, row0) do {                                          \
        _Pragma("unroll")                                                     \
        for (int it = 0; it < 8; it++) {                                      \
            int g = tid + 256 * it;                                           \
            int row = g >> 5, c16 = g & 31;                                   \
            size_t go = (size_t)(b * SS + (row0) + row) * FUSED + kvh * HD + c16 * 8; \
            cp_async16((dst) + row * FPITCH + c16 * 16, (src) + go);          \
        }                                                                     \
        asm volatile("cp.async.commit_group;");                               \
    } while (0)

    for (int tile = 0; tile < 2; tile++) {
        const int qb = (tile == 0) ? (15 - pairIdx) : pairIdx;
        const int q0 = qb * 128;
        const int ktmax = 2 * qb + 1;

        // Q tile: 128 rows
#pragma unroll
        for (int it = 0; it < 16; it++) {
            int g = tid + 256 * it;
            int row = g >> 5, c16 = g & 31;
            size_t go = (size_t)(b * SS + q0 + row) * FUSED + h * HD + c16 * 8;
            cp_async16(sQ + row * FPITCH + c16 * 16, qh + go);
        }
        asm volatile("cp.async.commit_group;");

        LOAD_KV(sK, kh, 0);

        float o[32][4];
#pragma unroll
        for (int d = 0; d < 32; d++)
#pragma unroll
            for (int c = 0; c < 4; c++) o[d][c] = 0.f;
        float m_[2] = {-1e30f, -1e30f};
        float l_[2] = {0.f, 0.f};

        for (int kt = 0; kt <= ktmax; kt++) {
            const int k0 = kt * 64;
            asm volatile("cp.async.wait_group 0;" ::: "memory");
            __syncthreads();

            LOAD_KV(sV, vh, k0);   // overlaps S-phase

            // ----- S-phase -----
            float s[8][4];
#pragma unroll
            for (int j = 0; j < 8; j++)
#pragma unroll
                for (int c = 0; c < 4; c++) s[j][c] = 0.f;

#pragma unroll 4
            for (int kc = 0; kc < 16; kc++) {
                uint32_t a[4];
                ldsm_x4(a, sQ + (uint32_t)(ra * FPITCH + (kc * 16 + (lid >> 4) * 8) * 2));
#pragma unroll
                for (int p = 0; p < 4; p++) {
                    uint32_t boff = (uint32_t)(
                        (p * 16 + ((lid >> 4) & 1) * 8 + (lid & 7)) * FPITCH
                        + (kc * 16 + ((lid >> 3) & 1) * 8) * 2);
                    uint32_t bbv[4];
                    ldsm_x4(bbv, sK + boff);
                    mma_f16(s[2 * p],     a, &bbv[0]);
                    mma_f16(s[2 * p + 1], a, &bbv[2]);
                }
            }

            __syncthreads();
            if (kt < ktmax) LOAD_KV(sK, kh, k0 + 64);   // overlaps softmax + PV

            // ----- causal mask -----
            if (k0 + 63 > q0 + wid * 16) {
#pragma unroll
                for (int j = 0; j < 8; j++)
#pragma unroll
                    for (int c = 0; c < 4; c++) {
                        int col = k0 + j * 8 + (lid & 3) * 2 + (c & 1);
                        int row = q0 + wid * 16 + rq + (c >> 1) * 8;
                        if (col > row) s[j][c] = -1e30f;
                    }
            }

            // ----- online softmax -----
            float alpha[2];
#pragma unroll
            for (int hh = 0; hh < 2; hh++) {
                float mx = -1e30f;
#pragma unroll
                for (int j = 0; j < 8; j++)
                    mx = fmaxf(mx, fmaxf(s[j][2 * hh], s[j][2 * hh + 1]));
                mx = fmaxf(mx, __shfl_xor_sync(0xffffffffu, mx, 1));
                mx = fmaxf(mx, __shfl_xor_sync(0xffffffffu, mx, 2));
                float mnew = fmaxf(m_[hh], mx);
                alpha[hh] = __expf(m_[hh] - mnew);
                m_[hh] = mnew;
                float sum = 0.f;
#pragma unroll
                for (int j = 0; j < 8; j++) {
                    float p0 = __expf(s[j][2 * hh] - mnew);
                    float p1 = __expf(s[j][2 * hh + 1] - mnew);
                    s[j][2 * hh] = p0;
                    s[j][2 * hh + 1] = p1;
                    sum += p0 + p1;
                }
                sum += __shfl_xor_sync(0xffffffffu, sum, 1);
                sum += __shfl_xor_sync(0xffffffffu, sum, 2);
                l_[hh] = l_[hh] * alpha[hh] + sum;
            }
#pragma unroll
            for (int d = 0; d < 32; d++) {
                o[d][0] *= alpha[0];
                o[d][1] *= alpha[0];
                o[d][2] *= alpha[1];
                o[d][3] *= alpha[1];
            }

            // ----- P -> fp16 fragments -----
            uint32_t p0[8], p1[8];
#pragma unroll
            for (int j = 0; j < 8; j++) {
                p0[j] = pack_h2(s[j][0], s[j][1]);
                p1[j] = pack_h2(s[j][2], s[j][3]);
            }

            if (kt < ktmax) {
                asm volatile("cp.async.wait_group 1;" ::: "memory");
            } else {
                asm volatile("cp.async.wait_group 0;" ::: "memory");
            }
            __syncthreads();

            // ----- PV phase -----
#pragma unroll
            for (int kc = 0; kc < 4; kc++) {
                uint32_t aP[4] = {p0[2 * kc], p1[2 * kc], p0[2 * kc + 1], p1[2 * kc + 1]};
#pragma unroll
                for (int dp = 0; dp < 16; dp++) {
                    uint32_t voff = (uint32_t)(
                        (kc * 16 + ((lid >> 3) & 1) * 8 + (lid & 7)) * FPITCH
                        + (dp * 16 + ((lid >> 4) & 1) * 8) * 2);
                    uint32_t bbv[4];
                    ldsm_x4t(bbv, sV + voff);
                    mma_f16(o[2 * dp],     aP, &bbv[0]);
                    mma_f16(o[2 * dp + 1], aP, &bbv[2]);
                }
            }
        }

        // ----- epilogue -----
        float inv[2] = {1.f / l_[0], 1.f / l_[1]};
#pragma unroll
        for (int hh = 0; hh < 2; hh++) {
            int row = q0 + wid * 16 + rq + 8 * hh;
            size_t base = (size_t)(b * SS + row) * QDIM + h * HD;
#pragma unroll
            for (int d = 0; d < 32; d++) {
                int col = d * 8 + (lid & 3) * 2;
                float v0 = o[d][2 * hh] * inv[hh];
                float v1 = o[d][2 * hh + 1] * inv[hh];
                *(uint32_t*)(ch + base + col) = pack_h2(v0, v1);
            }
        }
        __syncthreads();   // all warps done before next tile's Q/K loads
    }
#undef LOAD_KV
}

// ---------------------------------------------------------------------------
// launch
// ---------------------------------------------------------------------------
extern "C" void kernel_launch(void* const* d_in, const int* in_sizes, int n_in,
                              void* d_out, int out_size) {
    const float* x    = (const float*)d_in[0];
    const float* cosp = (const float*)d_in[2];
    const float* sinp = (const float*)d_in[3];
    const float* wq   = (const float*)d_in[4];
    const float* wk   = (const float*)d_in[5];
    const float* wv   = (const float*)d_in[6];
    const float* wo   = (const float*)d_in[7];
    const float* qg   = (const float*)d_in[8];
    const float* kg   = (const float*)d_in[9];
    float* out = (float*)d_out;

    float* pqkv;
    __half *pqkvh, *pxh, *pwf, *pwoh, *pch;
    cudaGetSymbolAddress((void**)&pqkv,  g_qkv);
    cudaGetSymbolAddress((void**)&pqkvh, g_qkvh);
    cudaGetSymbolAddress((void**)&pxh,   g_xh);
    cudaGetSymbolAddress((void**)&pwf,   g_wf);
    cudaGetSymbolAddress((void**)&pwoh,  g_woh);
    cudaGetSymbolAddress((void**)&pch,   g_ch);

    const int M = BB * SS;   // 4096

    cudaFuncSetAttribute(gemm_f16, cudaFuncAttributeMaxDynamicSharedMemorySize,
                         HSMEM_BYTES);
    cudaFuncSetAttribute(flash_f16, cudaFuncAttributeMaxDynamicSharedMemorySize,
                         FSMEM_BYTES);

    // merged converts (1 launch)
    cvt_all<<<(CVT_TOT + 255) / 256, 256>>>(x, wq, wk, wv, wo);

    // Fused QKV projection: [M, 4096] = x @ [wq|wk|wv]^T
    gemm_f16<<<dim3(FUSED / 128, M / 128), 512, HSMEM_BYTES>>>(
        pxh, pwf, pqkv, M, FUSED, DIN);

    // RMSNorm + RoPE + v-convert
    rms_rope2<<<dim3(M, 2), 256>>>(cosp, sinp, qg, kg);

    // Flash attention (paired q-tiles, 128 CTAs)
    flash_f16<<<dim3(8, NH, BB), 256, FSMEM_BYTES>>>(
        pqkvh, pqkvh + QDIM, pqkvh + QDIM + KVDIM, pch);

    // Output projection
    gemm_f16<<<dim3(QDIM / 128, M / 128), 512, HSMEM_BYTES>>>(
        pch, pwoh, out, M, QDIM, DIN);
}

// round 15
// speedup vs baseline: 1.4682x; 1.4682x over previous
#include <cuda_runtime.h>
#include <cuda_fp16.h>
#include <cstdint>
#include <math.h>

// Problem constants
#define BB   2
#define SS   2048
#define DIN  2048
#define NH   8
#define NKV  4
#define HD   256
#define QDIM  (NH*HD)    // 2048
#define KVDIM (NKV*HD)   // 1024
#define FUSED 4096       // q(2048) | k(1024) | v(1024)
#define SCALING 0.0625f
#define EPS 1e-6f

// ---------------------------------------------------------------------------
// Scratch (device globals)
// ---------------------------------------------------------------------------
__device__ float  g_qkv [(size_t)BB*SS*FUSED];   // fp32 pre-norm qkv
__device__ __half g_qkvh[(size_t)BB*SS*FUSED];   // fp16 post-norm/rope qkv
__device__ __half g_xh  [(size_t)BB*SS*DIN];
__device__ __half g_wf  [(size_t)FUSED*DIN];     // fused wq|wk|wv fp16
__device__ __half g_woh [(size_t)DIN*QDIM];
__device__ __half g_ch  [(size_t)BB*SS*QDIM];

// ---------------------------------------------------------------------------
// Helpers
// ---------------------------------------------------------------------------
__device__ __forceinline__ uint32_t smem_to_u32(const void* smem_ptr) {
    uint32_t addr;
    asm("{ .reg .u64 tmp; cvta.to.shared.u64 tmp, %1; cvt.u32.u64 %0, tmp; }"
        : "=r"(addr) : "l"(smem_ptr));
    return addr;
}
__device__ __forceinline__ void ldsm_x4(uint32_t* r, uint32_t addr) {
    asm volatile("ldmatrix.sync.aligned.m8n8.x4.shared.b16 {%0,%1,%2,%3}, [%4];"
                 : "=r"(r[0]), "=r"(r[1]), "=r"(r[2]), "=r"(r[3]) : "r"(addr));
}
__device__ __forceinline__ void ldsm_x4t(uint32_t* r, uint32_t addr) {
    asm volatile("ldmatrix.sync.aligned.m8n8.x4.trans.shared.b16 {%0,%1,%2,%3}, [%4];"
                 : "=r"(r[0]), "=r"(r[1]), "=r"(r[2]), "=r"(r[3]) : "r"(addr));
}
__device__ __forceinline__ void mma_f16(float* d, const uint32_t* a, const uint32_t* b) {
    asm volatile(
        "mma.sync.aligned.m16n8k16.row.col.f32.f16.f16.f32 "
        "{%0,%1,%2,%3}, {%4,%5,%6,%7}, {%8,%9}, {%0,%1,%2,%3};"
        : "+f"(d[0]), "+f"(d[1]), "+f"(d[2]), "+f"(d[3])
        : "r"(a[0]), "r"(a[1]), "r"(a[2]), "r"(a[3]), "r"(b[0]), "r"(b[1]));
}
__device__ __forceinline__ void cp_async16(uint32_t dst, const void* src) {
    asm volatile("cp.async.cg.shared.global [%0], [%1], 16;" :: "r"(dst), "l"(src));
}
__device__ __forceinline__ uint32_t pack_h2(float x0, float x1) {
    __half2 h = __floats2half2_rn(x0, x1);
    return *(uint32_t*)&h;
}

// ---------------------------------------------------------------------------
// Merged fp32 -> fp16 convert (one launch). Regions in float4 units.
// ---------------------------------------------------------------------------
#define CVT_N0 ((BB*SS*DIN)/4)
#define CVT_N1 ((QDIM*DIN)/4)
#define CVT_N2 ((KVDIM*DIN)/4)
#define CVT_N3 ((KVDIM*DIN)/4)
#define CVT_N4 ((DIN*QDIM)/4)
#define CVT_TOT (CVT_N0+CVT_N1+CVT_N2+CVT_N3+CVT_N4)

__global__ void cvt_all(const float* __restrict__ x,  const float* __restrict__ wq,
                        const float* __restrict__ wk, const float* __restrict__ wv,
                        const float* __restrict__ wo) {
    int i = blockIdx.x * blockDim.x + threadIdx.x;
    if (i >= CVT_TOT) return;
    const float* src;
    __half* dst;
    int j = i;
    if (j < CVT_N0) { src = x;  dst = g_xh; }
    else if ((j -= CVT_N0) < CVT_N1) { src = wq; dst = g_wf; }
    else if ((j -= CVT_N1) < CVT_N2) { src = wk; dst = g_wf + (size_t)QDIM * DIN; }
    else if ((j -= CVT_N2) < CVT_N3) { src = wv; dst = g_wf + (size_t)(QDIM + KVDIM) * DIN; }
    else { j -= CVT_N3; src = wo; dst = g_woh; }
    float4 v = ((const float4*)src)[j];
    uint2 r;
    r.x = pack_h2(v.x, v.y);
    r.y = pack_h2(v.z, v.w);
    ((uint2*)dst)[j] = r;
}

// ---------------------------------------------------------------------------
// HMMA GEMM (NT, fp16) — R8-proven config + B-frag preload (12 ldsm/chunk).
// Tile 128x128, BK=32, 256 threads, 8 warps (2x4), warp tile 64x32,
// 2-stage cp.async, 2 CTAs/SM.
// ---------------------------------------------------------------------------
#define HBK 32
#define HPITCH 80
#define HMAT_BYTES (128 * HPITCH)      // 10240
#define HSTAGE_BYTES (2 * HMAT_BYTES)  // 20480
#define HSMEM_BYTES (2 * HSTAGE_BYTES) // 40960

__global__ __launch_bounds__(256, 2)
void gemm_f16(const __half* __restrict__ A, const __half* __restrict__ B,
              float* __restrict__ C, int M, int N, int K) {
    extern __shared__ char smemc[];
    const uint32_t smem = smem_to_u32(smemc);
    const int tid = threadIdx.x;
    const int wid = tid >> 5;
    const int lid = tid & 31;
    const int warp_m = wid >> 2;     // 0-1
    const int warp_n = wid & 3;      // 0-3
    const int m0 = blockIdx.y * 128;
    const int n0 = blockIdx.x * 128;
    const int kchunks = K / HBK;     // 64

#define PREFETCH(cc) do {                                                     \
        const int s_ = (cc) & 1;                                              \
        const int k0_ = (cc) * HBK;                                           \
        _Pragma("unroll")                                                     \
        for (int it = 0; it < 4; it++) {                                      \
            int g = tid + 256 * it;                                           \
            int mat = g >> 9;                                                 \
            int idx = g & 511;                                                \
            int r = idx >> 2;                                                 \
            int q = idx & 3;                                                  \
            int rowg = (mat == 0 ? m0 : n0) + r;                              \
            const __half* src = (mat == 0 ? A : B) + (size_t)rowg * K + k0_ + q * 8; \
            uint32_t dst = smem + s_ * HSTAGE_BYTES + mat * HMAT_BYTES        \
                         + r * HPITCH + q * 16;                               \
            cp_async16(dst, src);                                             \
        }                                                                     \
        asm volatile("cp.async.commit_group;");                               \
    } while (0)

    float acc[4][4][4];
#pragma unroll
    for (int i = 0; i < 4; i++)
#pragma unroll
        for (int j = 0; j < 4; j++)
#pragma unroll
            for (int q = 0; q < 4; q++) acc[i][j][q] = 0.f;

    PREFETCH(0);

    for (int c = 0; c < kchunks; c++) {
        if (c + 1 < kchunks) {
            PREFETCH(c + 1);
            asm volatile("cp.async.wait_group 1;" ::: "memory");
        } else {
            asm volatile("cp.async.wait_group 0;" ::: "memory");
        }
        __syncthreads();

        const uint32_t sA = smem + (c & 1) * HSTAGE_BYTES;
        const uint32_t sB = sA + HMAT_BYTES;

        // --- preload ALL B fragments for both k16 steps (4 ldsm_x4) ---
        uint32_t bfr[2][4][2];
#pragma unroll
        for (int k16 = 0; k16 < 2; k16++) {
            const int kb2 = (k16 * 16 + (lid >> 4) * 8) * 2;
#pragma unroll
            for (int j = 0; j < 2; j++) {
                int rb = warp_n * 32 + j * 16 + (lid & 15);
                uint32_t t[4];
                ldsm_x4(t, sB + (uint32_t)(rb * HPITCH) + kb2);
                bfr[k16][2 * j][0]     = t[0]; bfr[k16][2 * j][1]     = t[2];
                bfr[k16][2 * j + 1][0] = t[1]; bfr[k16][2 * j + 1][1] = t[3];
            }
        }

        // --- A loads interleaved with MMA per k16 ---
#pragma unroll
        for (int k16 = 0; k16 < 2; k16++) {
            const int kb2 = (k16 * 16 + (lid >> 4) * 8) * 2;
            uint32_t a[4][4];
            {
                int ra = warp_m * 64 + (lid & 15);
#pragma unroll
                for (int i = 0; i < 4; i++)
                    ldsm_x4(a[i], sA + (uint32_t)((ra + i * 16) * HPITCH) + kb2);
            }
#pragma unroll
            for (int i = 0; i < 4; i++)
#pragma unroll
                for (int j = 0; j < 4; j++)
                    mma_f16(acc[i][j], a[i], bfr[k16][j]);
        }
        __syncthreads();
    }

    const int rbase = m0 + warp_m * 64 + (lid >> 2);
    const int cbase = n0 + warp_n * 32 + (lid & 3) * 2;
#pragma unroll
    for (int i = 0; i < 4; i++)
#pragma unroll
        for (int j = 0; j < 4; j++) {
            float* p0 = C + (size_t)(rbase + i * 16) * N + cbase + j * 8;
            float* p1 = C + (size_t)(rbase + i * 16 + 8) * N + cbase + j * 8;
            *(float2*)p0 = make_float2(acc[i][j][0], acc[i][j][1]);
            *(float2*)p1 = make_float2(acc[i][j][2], acc[i][j][3]);
        }
#undef PREFETCH
}

// ---------------------------------------------------------------------------
// RMSNorm + RoPE v2 (unchanged, proven).
// ---------------------------------------------------------------------------
__global__ void rms_rope2(const float* __restrict__ cosp,
                          const float* __restrict__ sinp,
                          const float* __restrict__ qg,
                          const float* __restrict__ kg) {
    const int bs = blockIdx.x;
    const int spos = bs & (SS - 1);
    const int wid = threadIdx.x >> 5, lane = threadIdx.x & 31;
    const int head = blockIdx.y * 8 + wid;   // 0..15

    int col0;
    if (head < 8)       col0 = head * HD;
    else if (head < 12) col0 = 2048 + (head - 8) * HD;
    else                col0 = 3072 + (head - 12) * HD;

    const float* src = g_qkv + (size_t)bs * FUSED + col0;
    __half* dst = g_qkvh + (size_t)bs * FUSED + col0;

    float v[8];
#pragma unroll
    for (int i = 0; i < 8; i++) v[i] = src[lane + 32 * i];

    if (head < 12) {
        float ssum = 0.f;
#pragma unroll
        for (int i = 0; i < 8; i++) ssum += v[i] * v[i];
#pragma unroll
        for (int off = 16; off >= 1; off >>= 1)
            ssum += __shfl_xor_sync(0xffffffffu, ssum, off);
        float rstd = rsqrtf(ssum * (1.0f / HD) + EPS);
        const float* gamma = (head < 8) ? qg : kg;
        float scale = (head < 8) ? SCALING : 1.0f;
        float xn[8];
#pragma unroll
        for (int i = 0; i < 8; i++)
            xn[i] = v[i] * rstd * (1.0f + gamma[lane + 32 * i]);
#pragma unroll
        for (int i = 0; i < 8; i++) {
            int d = lane + 32 * i;
            float rot = (i < 4) ? -xn[i + 4] : xn[i - 4];
            float o = (xn[i] * cosp[(size_t)spos * HD + d]
                     + rot * sinp[(size_t)spos * HD + d]) * scale;
            dst[d] = __float2half(o);
        }
    } else {
#pragma unroll
        for (int i = 0; i < 8; i++)
            dst[lane + 32 * i] = __float2half(v[i]);
    }
}

// ---------------------------------------------------------------------------
// Flash attention v3 (R8-proven, 142 us): complementary-paired q-tiles,
// BM=128, BN=64, 256 threads, 128 CTAs (single wave).
// ---------------------------------------------------------------------------
#define FPITCH 528
#define FQTILE (128 * FPITCH)               // 67584
#define FKTILE (64 * FPITCH)                // 33792
#define FSMEM_BYTES (FQTILE + 2 * FKTILE)   // 135168

__global__ __launch_bounds__(256)
void flash_f16(const __half* __restrict__ qh, const __half* __restrict__ kh,
               const __half* __restrict__ vh, __half* __restrict__ ch) {
    extern __shared__ char smemc[];
    const uint32_t smem = smem_to_u32(smemc);
    const uint32_t sQ = smem;
    const uint32_t sK = smem + FQTILE;
    const uint32_t sV = smem + FQTILE + FKTILE;

    const int pairIdx = blockIdx.x;          // 0..7
    const int h = blockIdx.y, b = blockIdx.z;
    const int kvh = h >> 1;
    const int tid = threadIdx.x, wid = tid >> 5, lid = tid & 31;

    const int ra = wid * 16 + (lid & 15);
    const int rq = (lid >> 2);

#define LOAD_KV(dst, src, row0) do {                                          \
        _Pragma("unroll")                                                     \
        for (int it = 0; it < 8; it++) {                                      \
            int g = tid + 256 * it;                                           \
            int row = g >> 5, c16 = g & 31;                                   \
            size_t go = (size_t)(b * SS + (row0) + row) * FUSED + kvh * HD + c16 * 8; \
            cp_async16((dst) + row * FPITCH + c16 * 16, (src) + go);          \
        }                                                                     \
        asm volatile("cp.async.commit_group;");                               \
    } while (0)

    for (int tile = 0; tile < 2; tile++) {
        const int qb = (tile == 0) ? (15 - pairIdx) : pairIdx;
        const int q0 = qb * 128;
        const int ktmax = 2 * qb + 1;

        // Q tile: 128 rows
#pragma unroll
        for (int it = 0; it < 16; it++) {
            int g = tid + 256 * it;
            int row = g >> 5, c16 = g & 31;
            size_t go = (size_t)(b * SS + q0 + row) * FUSED + h * HD + c16 * 8;
            cp_async16(sQ + row * FPITCH + c16 * 16, qh + go);
        }
        asm volatile("cp.async.commit_group;");

        LOAD_KV(sK, kh, 0);

        float o[32][4];
#pragma unroll
        for (int d = 0; d < 32; d++)
#pragma unroll
            for (int c = 0; c < 4; c++) o[d][c] = 0.f;
        float m_[2] = {-1e30f, -1e30f};
        float l_[2] = {0.f, 0.f};

        for (int kt = 0; kt <= ktmax; kt++) {
            const int k0 = kt * 64;
            asm volatile("cp.async.wait_group 0;" ::: "memory");
            __syncthreads();

            LOAD_KV(sV, vh, k0);   // overlaps S-phase

            // ----- S-phase -----
            float s[8][4];
#pragma unroll
            for (int j = 0; j < 8; j++)
#pragma unroll
                for (int c = 0; c < 4; c++) s[j][c] = 0.f;

#pragma unroll 4
            for (int kc = 0; kc < 16; kc++) {
                uint32_t a[4];
                ldsm_x4(a, sQ + (uint32_t)(ra * FPITCH + (kc * 16 + (lid >> 4) * 8) * 2));
#pragma unroll
                for (int p = 0; p < 4; p++) {
                    uint32_t boff = (uint32_t)(
                        (p * 16 + ((lid >> 4) & 1) * 8 + (lid & 7)) * FPITCH
                        + (kc * 16 + ((lid >> 3) & 1) * 8) * 2);
                    uint32_t bbv[4];
                    ldsm_x4(bbv, sK + boff);
                    mma_f16(s[2 * p],     a, &bbv[0]);
                    mma_f16(s[2 * p + 1], a, &bbv[2]);
                }
            }

            __syncthreads();
            if (kt < ktmax) LOAD_KV(sK, kh, k0 + 64);   // overlaps softmax + PV

            // ----- causal mask -----
            if (k0 + 63 > q0 + wid * 16) {
#pragma unroll
                for (int j = 0; j < 8; j++)
#pragma unroll
                    for (int c = 0; c < 4; c++) {
                        int col = k0 + j * 8 + (lid & 3) * 2 + (c & 1);
                        int row = q0 + wid * 16 + rq + (c >> 1) * 8;
                        if (col > row) s[j][c] = -1e30f;
                    }
            }

            // ----- online softmax -----
            float alpha[2];
#pragma unroll
            for (int hh = 0; hh < 2; hh++) {
                float mx = -1e30f;
#pragma unroll
                for (int j = 0; j < 8; j++)
                    mx = fmaxf(mx, fmaxf(s[j][2 * hh], s[j][2 * hh + 1]));
                mx = fmaxf(mx, __shfl_xor_sync(0xffffffffu, mx, 1));
                mx = fmaxf(mx, __shfl_xor_sync(0xffffffffu, mx, 2));
                float mnew = fmaxf(m_[hh], mx);
                alpha[hh] = __expf(m_[hh] - mnew);
                m_[hh] = mnew;
                float sum = 0.f;
#pragma unroll
                for (int j = 0; j < 8; j++) {
                    float p0 = __expf(s[j][2 * hh] - mnew);
                    float p1 = __expf(s[j][2 * hh + 1] - mnew);
                    s[j][2 * hh] = p0;
                    s[j][2 * hh + 1] = p1;
                    sum += p0 + p1;
                }
                sum += __shfl_xor_sync(0xffffffffu, sum, 1);
                sum += __shfl_xor_sync(0xffffffffu, sum, 2);
                l_[hh] = l_[hh] * alpha[hh] + sum;
            }
#pragma unroll
            for (int d = 0; d < 32; d++) {
                o[d][0] *= alpha[0];
                o[d][1] *= alpha[0];
                o[d][2] *= alpha[1];
                o[d][3] *= alpha[1];
            }

            // ----- P -> fp16 fragments -----
            uint32_t p0[8], p1[8];
#pragma unroll
            for (int j = 0; j < 8; j++) {
                p0[j] = pack_h2(s[j][0], s[j][1]);
                p1[j] = pack_h2(s[j][2], s[j][3]);
            }

            if (kt < ktmax) {
                asm volatile("cp.async.wait_group 1;" ::: "memory");
            } else {
                asm volatile("cp.async.wait_group 0;" ::: "memory");
            }
            __syncthreads();

            // ----- PV phase -----
#pragma unroll
            for (int kc = 0; kc < 4; kc++) {
                uint32_t aP[4] = {p0[2 * kc], p1[2 * kc], p0[2 * kc + 1], p1[2 * kc + 1]};
#pragma unroll
                for (int dp = 0; dp < 16; dp++) {
                    uint32_t voff = (uint32_t)(
                        (kc * 16 + ((lid >> 3) & 1) * 8 + (lid & 7)) * FPITCH
                        + (dp * 16 + ((lid >> 4) & 1) * 8) * 2);
                    uint32_t bbv[4];
                    ldsm_x4t(bbv, sV + voff);
                    mma_f16(o[2 * dp],     aP, &bbv[0]);
                    mma_f16(o[2 * dp + 1], aP, &bbv[2]);
                }
            }
        }

        // ----- epilogue -----
        float inv[2] = {1.f / l_[0], 1.f / l_[1]};
#pragma unroll
        for (int hh = 0; hh < 2; hh++) {
            int row = q0 + wid * 16 + rq + 8 * hh;
            size_t base = (size_t)(b * SS + row) * QDIM + h * HD;
#pragma unroll
            for (int d = 0; d < 32; d++) {
                int col = d * 8 + (lid & 3) * 2;
                float v0 = o[d][2 * hh] * inv[hh];
                float v1 = o[d][2 * hh + 1] * inv[hh];
                *(uint32_t*)(ch + base + col) = pack_h2(v0, v1);
            }
        }
        __syncthreads();   // all warps done before next tile's Q/K loads
    }
#undef LOAD_KV
}

// ---------------------------------------------------------------------------
// launch
// ---------------------------------------------------------------------------
extern "C" void kernel_launch(void* const* d_in, const int* in_sizes, int n_in,
                              void* d_out, int out_size) {
    const float* x    = (const float*)d_in[0];
    const float* cosp = (const float*)d_in[2];
    const float* sinp = (const float*)d_in[3];
    const float* wq   = (const float*)d_in[4];
    const float* wk   = (const float*)d_in[5];
    const float* wv   = (const float*)d_in[6];
    const float* wo   = (const float*)d_in[7];
    const float* qg   = (const float*)d_in[8];
    const float* kg   = (const float*)d_in[9];
    float* out = (float*)d_out;

    float* pqkv;
    __half *pqkvh, *pxh, *pwf, *pwoh, *pch;
    cudaGetSymbolAddress((void**)&pqkv,  g_qkv);
    cudaGetSymbolAddress((void**)&pqkvh, g_qkvh);
    cudaGetSymbolAddress((void**)&pxh,   g_xh);
    cudaGetSymbolAddress((void**)&pwf,   g_wf);
    cudaGetSymbolAddress((void**)&pwoh,  g_woh);
    cudaGetSymbolAddress((void**)&pch,   g_ch);

    const int M = BB * SS;   // 4096

    cudaFuncSetAttribute(gemm_f16, cudaFuncAttributeMaxDynamicSharedMemorySize,
                         HSMEM_BYTES);
    cudaFuncSetAttribute(flash_f16, cudaFuncAttributeMaxDynamicSharedMemorySize,
                         FSMEM_BYTES);

    // merged converts (1 launch)
    cvt_all<<<(CVT_TOT + 255) / 256, 256>>>(x, wq, wk, wv, wo);

    // Fused QKV projection: [M, 4096] = x @ [wq|wk|wv]^T
    gemm_f16<<<dim3(FUSED / 128, M / 128), 256, HSMEM_BYTES>>>(
        pxh, pwf, pqkv, M, FUSED, DIN);

    // RMSNorm + RoPE + v-convert
    rms_rope2<<<dim3(M, 2), 256>>>(cosp, sinp, qg, kg);

    // Flash attention (paired q-tiles, 128 CTAs)
    flash_f16<<<dim3(8, NH, BB), 256, FSMEM_BYTES>>>(
        pqkvh, pqkvh + QDIM, pqkvh + QDIM + KVDIM, pch);

    // Output projection
    gemm_f16<<<dim3(QDIM / 128, M / 128), 256, HSMEM_BYTES>>>(
        pch, pwoh, out, M, QDIM, DIN);
}

// round 16
// speedup vs baseline: 1.6564x; 1.1282x over previous
#include <cuda_runtime.h>
#include <cuda_fp16.h>
#include <cstdint>
#include <math.h>

// Problem constants
#define BB   2
#define SS   2048
#define DIN  2048
#define NH   8
#define NKV  4
#define HD   256
#define QDIM  (NH*HD)    // 2048
#define KVDIM (NKV*HD)   // 1024
#define FUSED 4096       // q(2048) | k(1024) | v(1024)
#define SCALING 0.0625f
#define EPS 1e-6f

// ---------------------------------------------------------------------------
// Scratch (device globals)
// ---------------------------------------------------------------------------
__device__ float  g_qkv [(size_t)BB*SS*FUSED];   // fp32 pre-norm qkv
__device__ __half g_qkvh[(size_t)BB*SS*FUSED];   // fp16 post-norm/rope qkv
__device__ __half g_xh  [(size_t)BB*SS*DIN];
__device__ __half g_wf  [(size_t)FUSED*DIN];     // fused wq|wk|wv fp16
__device__ __half g_woh [(size_t)DIN*QDIM];
__device__ __half g_ch  [(size_t)BB*SS*QDIM];

// ---------------------------------------------------------------------------
// Helpers
// ---------------------------------------------------------------------------
__device__ __forceinline__ uint32_t smem_to_u32(const void* smem_ptr) {
    uint32_t addr;
    asm("{ .reg .u64 tmp; cvta.to.shared.u64 tmp, %1; cvt.u32.u64 %0, tmp; }"
        : "=r"(addr) : "l"(smem_ptr));
    return addr;
}
__device__ __forceinline__ void ldsm_x4(uint32_t* r, uint32_t addr) {
    asm volatile("ldmatrix.sync.aligned.m8n8.x4.shared.b16 {%0,%1,%2,%3}, [%4];"
                 : "=r"(r[0]), "=r"(r[1]), "=r"(r[2]), "=r"(r[3]) : "r"(addr));
}
__device__ __forceinline__ void ldsm_x4t(uint32_t* r, uint32_t addr) {
    asm volatile("ldmatrix.sync.aligned.m8n8.x4.trans.shared.b16 {%0,%1,%2,%3}, [%4];"
                 : "=r"(r[0]), "=r"(r[1]), "=r"(r[2]), "=r"(r[3]) : "r"(addr));
}
__device__ __forceinline__ void ldsm_x2(uint32_t& r0, uint32_t& r1, uint32_t addr) {
    asm volatile("ldmatrix.sync.aligned.m8n8.x2.shared.b16 {%0,%1}, [%2];"
                 : "=r"(r0), "=r"(r1) : "r"(addr));
}
__device__ __forceinline__ void mma_f16(float* d, const uint32_t* a, const uint32_t* b) {
    asm volatile(
        "mma.sync.aligned.m16n8k16.row.col.f32.f16.f16.f32 "
        "{%0,%1,%2,%3}, {%4,%5,%6,%7}, {%8,%9}, {%0,%1,%2,%3};"
        : "+f"(d[0]), "+f"(d[1]), "+f"(d[2]), "+f"(d[3])
        : "r"(a[0]), "r"(a[1]), "r"(a[2]), "r"(a[3]), "r"(b[0]), "r"(b[1]));
}
__device__ __forceinline__ void cp_async16(uint32_t dst, const void* src) {
    asm volatile("cp.async.cg.shared.global [%0], [%1], 16;" :: "r"(dst), "l"(src));
}
__device__ __forceinline__ uint32_t pack_h2(float x0, float x1) {
    __half2 h = __floats2half2_rn(x0, x1);
    return *(uint32_t*)&h;
}

// ---------------------------------------------------------------------------
// Merged fp32 -> fp16 convert (one launch). Regions in float4 units.
// ---------------------------------------------------------------------------
#define CVT_N0 ((BB*SS*DIN)/4)
#define CVT_N1 ((QDIM*DIN)/4)
#define CVT_N2 ((KVDIM*DIN)/4)
#define CVT_N3 ((KVDIM*DIN)/4)
#define CVT_N4 ((DIN*QDIM)/4)
#define CVT_TOT (CVT_N0+CVT_N1+CVT_N2+CVT_N3+CVT_N4)

__global__ void cvt_all(const float* __restrict__ x,  const float* __restrict__ wq,
                        const float* __restrict__ wk, const float* __restrict__ wv,
                        const float* __restrict__ wo) {
    int i = blockIdx.x * blockDim.x + threadIdx.x;
    if (i >= CVT_TOT) return;
    const float* src;
    __half* dst;
    int j = i;
    if (j < CVT_N0) { src = x;  dst = g_xh; }
    else if ((j -= CVT_N0) < CVT_N1) { src = wq; dst = g_wf; }
    else if ((j -= CVT_N1) < CVT_N2) { src = wk; dst = g_wf + (size_t)QDIM * DIN; }
    else if ((j -= CVT_N2) < CVT_N3) { src = wv; dst = g_wf + (size_t)(QDIM + KVDIM) * DIN; }
    else { j -= CVT_N3; src = wo; dst = g_woh; }
    float4 v = ((const float4*)src)[j];
    uint2 r;
    r.x = pack_h2(v.x, v.y);
    r.y = pack_h2(v.z, v.w);
    ((uint2*)dst)[j] = r;
}

// ---------------------------------------------------------------------------
// HMMA GEMM (NT, fp16) — EXACT R8 champion config.
// Tile 128x128, BK=32, 256 threads, 8 warps (2x4), warp tile 64x32, 2 CTAs/SM.
// ---------------------------------------------------------------------------
#define HBK 32
#define HPITCH 80
#define HMAT_BYTES (128 * HPITCH)      // 10240
#define HSTAGE_BYTES (2 * HMAT_BYTES)  // 20480
#define HSMEM_BYTES (2 * HSTAGE_BYTES) // 40960

__global__ __launch_bounds__(256, 2)
void gemm_f16(const __half* __restrict__ A, const __half* __restrict__ B,
              float* __restrict__ C, int M, int N, int K) {
    extern __shared__ char smemc[];
    const uint32_t smem = smem_to_u32(smemc);
    const int tid = threadIdx.x;
    const int wid = tid >> 5;
    const int lid = tid & 31;
    const int warp_m = wid >> 2;
    const int warp_n = wid & 3;
    const int m0 = blockIdx.y * 128;
    const int n0 = blockIdx.x * 128;
    const int kchunks = K / HBK;

#define PREFETCH(cc) do {                                                     \
        const int s_ = (cc) & 1;                                              \
        const int k0_ = (cc) * HBK;                                           \
        _Pragma("unroll")                                                     \
        for (int it = 0; it < 4; it++) {                                      \
            int g = tid + 256 * it;                                           \
            int mat = g >> 9;                                                 \
            int idx = g & 511;                                                \
            int r = idx >> 2;                                                 \
            int q = idx & 3;                                                  \
            int rowg = (mat == 0 ? m0 : n0) + r;                              \
            const __half* src = (mat == 0 ? A : B) + (size_t)rowg * K + k0_ + q * 8; \
            uint32_t dst = smem + s_ * HSTAGE_BYTES + mat * HMAT_BYTES        \
                         + r * HPITCH + q * 16;                               \
            cp_async16(dst, src);                                             \
        }                                                                     \
        asm volatile("cp.async.commit_group;");                               \
    } while (0)

    float acc[4][4][4];
#pragma unroll
    for (int i = 0; i < 4; i++)
#pragma unroll
        for (int j = 0; j < 4; j++)
#pragma unroll
            for (int q = 0; q < 4; q++) acc[i][j][q] = 0.f;

    PREFETCH(0);

    for (int c = 0; c < kchunks; c++) {
        if (c + 1 < kchunks) {
            PREFETCH(c + 1);
            asm volatile("cp.async.wait_group 1;" ::: "memory");
        } else {
            asm volatile("cp.async.wait_group 0;" ::: "memory");
        }
        __syncthreads();

        const uint32_t stage = smem + (c & 1) * HSTAGE_BYTES;
        const uint32_t sA = stage;
        const uint32_t sB = stage + HMAT_BYTES;

#pragma unroll
        for (int k16 = 0; k16 < 2; k16++) {
            const int coff = k16 * 16;
            uint32_t b[4][2];
            {
                int i15 = lid & 15;
                int rb = warp_n * 32 + (i15 & 7);
                int kb = coff + ((i15 >> 3) & 1) * 8;
#pragma unroll
                for (int j = 0; j < 4; j++) {
                    uint32_t off = (uint32_t)((rb + j * 8) * HPITCH + kb * 2);
                    ldsm_x2(b[j][0], b[j][1], sB + off);
                }
            }
            uint32_t a[4][4];
            {
                int ra = warp_m * 64 + (lid & 15);
                int ka = coff + (lid >> 4) * 8;
#pragma unroll
                for (int i = 0; i < 4; i++)
                    ldsm_x4(a[i], sA + (uint32_t)((ra + i * 16) * HPITCH + ka * 2));
            }
#pragma unroll
            for (int i = 0; i < 4; i++)
#pragma unroll
                for (int j = 0; j < 4; j++)
                    mma_f16(acc[i][j], a[i], b[j]);
        }
        __syncthreads();
    }

    const int rbase = m0 + warp_m * 64 + (lid >> 2);
    const int cbase = n0 + warp_n * 32 + (lid & 3) * 2;
#pragma unroll
    for (int i = 0; i < 4; i++)
#pragma unroll
        for (int j = 0; j < 4; j++) {
            float* p0 = C + (size_t)(rbase + i * 16) * N + cbase + j * 8;
            float* p1 = C + (size_t)(rbase + i * 16 + 8) * N + cbase + j * 8;
            *(float2*)p0 = make_float2(acc[i][j][0], acc[i][j][1]);
            *(float2*)p1 = make_float2(acc[i][j][2], acc[i][j][3]);
        }
#undef PREFETCH
}

// ---------------------------------------------------------------------------
// RMSNorm + RoPE v2 (unchanged, proven).
// ---------------------------------------------------------------------------
__global__ void rms_rope2(const float* __restrict__ cosp,
                          const float* __restrict__ sinp,
                          const float* __restrict__ qg,
                          const float* __restrict__ kg) {
    const int bs = blockIdx.x;
    const int spos = bs & (SS - 1);
    const int wid = threadIdx.x >> 5, lane = threadIdx.x & 31;
    const int head = blockIdx.y * 8 + wid;   // 0..15

    int col0;
    if (head < 8)       col0 = head * HD;
    else if (head < 12) col0 = 2048 + (head - 8) * HD;
    else                col0 = 3072 + (head - 12) * HD;

    const float* src = g_qkv + (size_t)bs * FUSED + col0;
    __half* dst = g_qkvh + (size_t)bs * FUSED + col0;

    float v[8];
#pragma unroll
    for (int i = 0; i < 8; i++) v[i] = src[lane + 32 * i];

    if (head < 12) {
        float ssum = 0.f;
#pragma unroll
        for (int i = 0; i < 8; i++) ssum += v[i] * v[i];
#pragma unroll
        for (int off = 16; off >= 1; off >>= 1)
            ssum += __shfl_xor_sync(0xffffffffu, ssum, off);
        float rstd = rsqrtf(ssum * (1.0f / HD) + EPS);
        const float* gamma = (head < 8) ? qg : kg;
        float scale = (head < 8) ? SCALING : 1.0f;
        float xn[8];
#pragma unroll
        for (int i = 0; i < 8; i++)
            xn[i] = v[i] * rstd * (1.0f + gamma[lane + 32 * i]);
#pragma unroll
        for (int i = 0; i < 8; i++) {
            int d = lane + 32 * i;
            float rot = (i < 4) ? -xn[i + 4] : xn[i - 4];
            float o = (xn[i] * cosp[(size_t)spos * HD + d]
                     + rot * sinp[(size_t)spos * HD + d]) * scale;
            dst[d] = __float2half(o);
        }
    } else {
#pragma unroll
        for (int i = 0; i < 8; i++)
            dst[lane + 32 * i] = __float2half(v[i]);
    }
}

// ---------------------------------------------------------------------------
// Flash attention v4: paired q-tiles (R8) + PV re-tiled 2x4 through smem P.
// S-phase/softmax: warp owns 16 q-rows (unchanged).
// PV: P (fp16) via smem; warps re-tile as (warp_m2=wid&1: 64 rows) x
// (warp_n2=wid>>2? no: wid>>1: 64 dims). V fragments shared across 4 mi -> V
// ldsm traffic cut 4x.
// ---------------------------------------------------------------------------
#define FPITCH 528
#define PPITCH 144
#define FQTILE (128 * FPITCH)               // 67584
#define FKTILE (64 * FPITCH)                // 33792
#define SP_OFF    (FQTILE + 2 * FKTILE)     // 135168
#define ALPHA_OFF (SP_OFF + 128 * PPITCH)   // +18432 = 153600
#define LINV_OFF  (ALPHA_OFF + 512)
#define FSMEM_BYTES (LINV_OFF + 512)        // 154624

__global__ __launch_bounds__(256)
void flash_f16(const __half* __restrict__ qh, const __half* __restrict__ kh,
               const __half* __restrict__ vh, __half* __restrict__ ch) {
    extern __shared__ char smemc[];
    const uint32_t smem = smem_to_u32(smemc);
    const uint32_t sQ = smem;
    const uint32_t sK = smem + FQTILE;
    const uint32_t sV = smem + FQTILE + FKTILE;
    const uint32_t sP = smem + SP_OFF;
    float* alphaP = (float*)(smemc + ALPHA_OFF);
    float* linvP  = (float*)(smemc + LINV_OFF);

    const int pairIdx = blockIdx.x;          // 0..7
    const int h = blockIdx.y, b = blockIdx.z;
    const int kvh = h >> 1;
    const int tid = threadIdx.x, wid = tid >> 5, lid = tid & 31;
    const int warp_m2 = wid & 1;             // PV row group (64 rows)
    const int warp_n2 = wid >> 1;            // PV dim group (64 dims)

    const int ra = wid * 16 + (lid & 15);
    const int rq = (lid >> 2);

#define LOAD_KV(dst, src, row0) do {                                          \
        _Pragma("unroll")                                                     \
        for (int it = 0; it < 8; it++) {                                      \
            int g = tid + 256 * it;                                           \
            int row = g >> 5, c16 = g & 31;                                   \
            size_t go = (size_t)(b * SS + (row0) + row) * FUSED + kvh * HD + c16 * 8; \
            cp_async16((dst) + row * FPITCH + c16 * 16, (src) + go);          \
        }                                                                     \
        asm volatile("cp.async.commit_group;");                               \
    } while (0)

    for (int tile = 0; tile < 2; tile++) {
        const int qb = (tile == 0) ? (15 - pairIdx) : pairIdx;
        const int q0 = qb * 128;
        const int ktmax = 2 * qb + 1;

        // Q tile: 128 rows
#pragma unroll
        for (int it = 0; it < 16; it++) {
            int g = tid + 256 * it;
            int row = g >> 5, c16 = g & 31;
            size_t go = (size_t)(b * SS + q0 + row) * FUSED + h * HD + c16 * 8;
            cp_async16(sQ + row * FPITCH + c16 * 16, qh + go);
        }
        asm volatile("cp.async.commit_group;");

        LOAD_KV(sK, kh, 0);

        // PV accumulator: [mi 4 rows-of-16][dp 8 dims-of-8][4]
        float o2[4][8][4];
#pragma unroll
        for (int mi = 0; mi < 4; mi++)
#pragma unroll
            for (int dp = 0; dp < 8; dp++)
#pragma unroll
                for (int c = 0; c < 4; c++) o2[mi][dp][c] = 0.f;
        float m_[2] = {-1e30f, -1e30f};
        float l_[2] = {0.f, 0.f};

        for (int kt = 0; kt <= ktmax; kt++) {
            const int k0 = kt * 64;
            asm volatile("cp.async.wait_group 0;" ::: "memory");
            __syncthreads();

            LOAD_KV(sV, vh, k0);   // overlaps S-phase

            // ----- S-phase (warp owns 16 q-rows; unchanged) -----
            float s[8][4];
#pragma unroll
            for (int j = 0; j < 8; j++)
#pragma unroll
                for (int c = 0; c < 4; c++) s[j][c] = 0.f;

#pragma unroll 4
            for (int kc = 0; kc < 16; kc++) {
                uint32_t a[4];
                ldsm_x4(a, sQ + (uint32_t)(ra * FPITCH + (kc * 16 + (lid >> 4) * 8) * 2));
#pragma unroll
                for (int p = 0; p < 4; p++) {
                    uint32_t boff = (uint32_t)(
                        (p * 16 + ((lid >> 4) & 1) * 8 + (lid & 7)) * FPITCH
                        + (kc * 16 + ((lid >> 3) & 1) * 8) * 2);
                    uint32_t bbv[4];
                    ldsm_x4(bbv, sK + boff);
                    mma_f16(s[2 * p],     a, &bbv[0]);
                    mma_f16(s[2 * p + 1], a, &bbv[2]);
                }
            }

            __syncthreads();
            if (kt < ktmax) LOAD_KV(sK, kh, k0 + 64);   // overlaps softmax + PV

            // ----- causal mask -----
            if (k0 + 63 > q0 + wid * 16) {
#pragma unroll
                for (int j = 0; j < 8; j++)
#pragma unroll
                    for (int c = 0; c < 4; c++) {
                        int col = k0 + j * 8 + (lid & 3) * 2 + (c & 1);
                        int row = q0 + wid * 16 + rq + (c >> 1) * 8;
                        if (col > row) s[j][c] = -1e30f;
                    }
            }

            // ----- online softmax (unchanged math) -----
            float alpha[2];
#pragma unroll
            for (int hh = 0; hh < 2; hh++) {
                float mx = -1e30f;
#pragma unroll
                for (int j = 0; j < 8; j++)
                    mx = fmaxf(mx, fmaxf(s[j][2 * hh], s[j][2 * hh + 1]));
                mx = fmaxf(mx, __shfl_xor_sync(0xffffffffu, mx, 1));
                mx = fmaxf(mx, __shfl_xor_sync(0xffffffffu, mx, 2));
                float mnew = fmaxf(m_[hh], mx);
                alpha[hh] = __expf(m_[hh] - mnew);
                m_[hh] = mnew;
                float sum = 0.f;
#pragma unroll
                for (int j = 0; j < 8; j++) {
                    float p0 = __expf(s[j][2 * hh] - mnew);
                    float p1 = __expf(s[j][2 * hh + 1] - mnew);
                    s[j][2 * hh] = p0;
                    s[j][2 * hh + 1] = p1;
                    sum += p0 + p1;
                }
                sum += __shfl_xor_sync(0xffffffffu, sum, 1);
                sum += __shfl_xor_sync(0xffffffffu, sum, 2);
                l_[hh] = l_[hh] * alpha[hh] + sum;
            }

            // ----- store alpha + P (fp16) to smem -----
            if ((lid & 3) == 0) {
                alphaP[wid * 16 + rq]     = alpha[0];
                alphaP[wid * 16 + rq + 8] = alpha[1];
            }
#pragma unroll
            for (int hh = 0; hh < 2; hh++) {
                int prow = wid * 16 + rq + 8 * hh;
#pragma unroll
                for (int j = 0; j < 8; j++) {
                    uint32_t pk = pack_h2(s[j][2 * hh], s[j][2 * hh + 1]);
                    *(uint32_t*)(smemc + SP_OFF + prow * PPITCH
                                 + (j * 8 + (lid & 3) * 2) * 2) = pk;
                }
            }

            // wait V (+ make P/alpha visible to all warps)
            if (kt < ktmax) {
                asm volatile("cp.async.wait_group 1;" ::: "memory");
            } else {
                asm volatile("cp.async.wait_group 0;" ::: "memory");
            }
            __syncthreads();

            // ----- rescale O by row-matched alpha -----
            float al[4][2];
#pragma unroll
            for (int mi = 0; mi < 4; mi++) {
                al[mi][0] = alphaP[warp_m2 * 64 + mi * 16 + (lid >> 2)];
                al[mi][1] = alphaP[warp_m2 * 64 + mi * 16 + (lid >> 2) + 8];
            }
#pragma unroll
            for (int mi = 0; mi < 4; mi++)
#pragma unroll
                for (int dp = 0; dp < 8; dp++) {
                    o2[mi][dp][0] *= al[mi][0];
                    o2[mi][dp][1] *= al[mi][0];
                    o2[mi][dp][2] *= al[mi][1];
                    o2[mi][dp][3] *= al[mi][1];
                }

            // ----- PV phase: warp tile 64 rows x 64 dims -----
#pragma unroll
            for (int kc = 0; kc < 4; kc++) {
                uint32_t aP[4][4];
#pragma unroll
                for (int mi = 0; mi < 4; mi++)
                    ldsm_x4(aP[mi], sP + (uint32_t)(
                        (warp_m2 * 64 + mi * 16 + (lid & 15)) * PPITCH
                        + (kc * 16 + (lid >> 4) * 8) * 2));
#pragma unroll
                for (int dg = 0; dg < 4; dg++) {
                    uint32_t voff = (uint32_t)(
                        (kc * 16 + ((lid >> 3) & 1) * 8 + (lid & 7)) * FPITCH
                        + (warp_n2 * 64 + dg * 16 + ((lid >> 4) & 1) * 8) * 2);
                    uint32_t bbv[4];
                    ldsm_x4t(bbv, sV + voff);
#pragma unroll
                    for (int mi = 0; mi < 4; mi++) {
                        mma_f16(o2[mi][2 * dg],     aP[mi], &bbv[0]);
                        mma_f16(o2[mi][2 * dg + 1], aP[mi], &bbv[2]);
                    }
                }
            }
        }

        // ----- epilogue: share 1/l, normalize, write ctx -----
        if ((lid & 3) == 0) {
            linvP[wid * 16 + rq]     = 1.f / l_[0];
            linvP[wid * 16 + rq + 8] = 1.f / l_[1];
        }
        __syncthreads();
#pragma unroll
        for (int mi = 0; mi < 4; mi++)
#pragma unroll
            for (int half = 0; half < 2; half++) {
                int r = warp_m2 * 64 + mi * 16 + (lid >> 2) + 8 * half;
                float inv = linvP[r];
                size_t base = (size_t)(b * SS + q0 + r) * QDIM + h * HD;
#pragma unroll
                for (int dp = 0; dp < 8; dp++) {
                    int col = warp_n2 * 64 + dp * 8 + (lid & 3) * 2;
                    *(uint32_t*)(ch + base + col) =
                        pack_h2(o2[mi][dp][2 * half] * inv,
                                o2[mi][dp][2 * half + 1] * inv);
                }
            }
        __syncthreads();   // all warps done before next tile's loads
    }
#undef LOAD_KV
}

// ---------------------------------------------------------------------------
// launch
// ---------------------------------------------------------------------------
extern "C" void kernel_launch(void* const* d_in, const int* in_sizes, int n_in,
                              void* d_out, int out_size) {
    const float* x    = (const float*)d_in[0];
    const float* cosp = (const float*)d_in[2];
    const float* sinp = (const float*)d_in[3];
    const float* wq   = (const float*)d_in[4];
    const float* wk   = (const float*)d_in[5];
    const float* wv   = (const float*)d_in[6];
    const float* wo   = (const float*)d_in[7];
    const float* qg   = (const float*)d_in[8];
    const float* kg   = (const float*)d_in[9];
    float* out = (float*)d_out;

    float* pqkv;
    __half *pqkvh, *pxh, *pwf, *pwoh, *pch;
    cudaGetSymbolAddress((void**)&pqkv,  g_qkv);
    cudaGetSymbolAddress((void**)&pqkvh, g_qkvh);
    cudaGetSymbolAddress((void**)&pxh,   g_xh);
    cudaGetSymbolAddress((void**)&pwf,   g_wf);
    cudaGetSymbolAddress((void**)&pwoh,  g_woh);
    cudaGetSymbolAddress((void**)&pch,   g_ch);

    const int M = BB * SS;   // 4096

    cudaFuncSetAttribute(gemm_f16, cudaFuncAttributeMaxDynamicSharedMemorySize,
                         HSMEM_BYTES);
    cudaFuncSetAttribute(flash_f16, cudaFuncAttributeMaxDynamicSharedMemorySize,
                         FSMEM_BYTES);

    // merged converts (1 launch)
    cvt_all<<<(CVT_TOT + 255) / 256, 256>>>(x, wq, wk, wv, wo);

    // Fused QKV projection: [M, 4096] = x @ [wq|wk|wv]^T
    gemm_f16<<<dim3(FUSED / 128, M / 128), 256, HSMEM_BYTES>>>(
        pxh, pwf, pqkv, M, FUSED, DIN);

    // RMSNorm + RoPE + v-convert
    rms_rope2<<<dim3(M, 2), 256>>>(cosp, sinp, qg, kg);

    // Flash attention (paired q-tiles, 128 CTAs)
    flash_f16<<<dim3(8, NH, BB), 256, FSMEM_BYTES>>>(
        pqkvh, pqkvh + QDIM, pqkvh + QDIM + KVDIM, pch);

    // Output projection
    gemm_f16<<<dim3(QDIM / 128, M / 128), 256, HSMEM_BYTES>>>(
        pch, pwoh, out, M, QDIM, DIN);
}